// round 16
// baseline (speedup 1.0000x reference)
#include <cuda_runtime.h>
#include <cuda_bf16.h>
#include <cstdint>
#include <math.h>

// ---------------- problem constants ----------------
#define BATCH 2
#define SEQ   2048
#define EMBED 1024
#define HEADS 16
#define HD    64
#define FF    4096
#define MTOK  (BATCH*SEQ)          // 4096
#define QKVN  (3*EMBED)            // 3072

typedef __nv_bfloat16 bf16;

// ---------------- device scratch ----------------
__device__ __align__(16) float g_qkv    [(size_t)MTOK*QKVN];
__device__ __align__(16) float g_x2     [(size_t)MTOK*EMBED];

__device__ __align__(16) bf16 g_nrm_h  [(size_t)MTOK*EMBED];
__device__ __align__(16) bf16 g_nrm_l  [(size_t)MTOK*EMBED];
__device__ __align__(16) bf16 g_wqkvT_h[(size_t)QKVN*EMBED];
__device__ __align__(16) bf16 g_wqkvT_l[(size_t)QKVN*EMBED];
__device__ __align__(16) bf16 g_q_h    [(size_t)BATCH*HEADS*SEQ*HD];
__device__ __align__(16) bf16 g_q_l    [(size_t)BATCH*HEADS*SEQ*HD];
__device__ __align__(16) bf16 g_k_h    [(size_t)BATCH*HEADS*SEQ*HD];
__device__ __align__(16) bf16 g_k_l    [(size_t)BATCH*HEADS*SEQ*HD];
__device__ __align__(16) bf16 g_vT_h   [(size_t)BATCH*HEADS*HD*SEQ];
__device__ __align__(16) bf16 g_vT_l   [(size_t)BATCH*HEADS*HD*SEQ];
__device__ __align__(16) bf16 g_attn_h [(size_t)MTOK*EMBED];
__device__ __align__(16) bf16 g_attn_l [(size_t)MTOK*EMBED];
__device__ __align__(16) bf16 g_woT_h  [(size_t)EMBED*EMBED];
__device__ __align__(16) bf16 g_woT_l  [(size_t)EMBED*EMBED];
__device__ __align__(16) bf16 g_n2_h   [(size_t)MTOK*EMBED];
__device__ __align__(16) bf16 g_n2_l   [(size_t)MTOK*EMBED];
__device__ __align__(16) bf16 g_w1T_h  [(size_t)FF*EMBED];
__device__ __align__(16) bf16 g_w1T_l  [(size_t)FF*EMBED];
__device__ __align__(16) bf16 g_ff1_h  [(size_t)MTOK*FF];
__device__ __align__(16) bf16 g_ff1_l  [(size_t)MTOK*FF];
__device__ __align__(16) bf16 g_w2T_h  [(size_t)EMBED*FF];
__device__ __align__(16) bf16 g_w2T_l  [(size_t)EMBED*FF];

// ---------------- PTX helpers (sm_80-level baseline only) ----------------
__device__ __forceinline__ uint32_t smem_u32(const void* p) {
    uint32_t a;
    asm("{ .reg .u64 t; cvta.to.shared.u64 t, %1; cvt.u32.u64 %0, t; }" : "=r"(a) : "l"(p));
    return a;
}
#define CP16(dst, src) \
    asm volatile("cp.async.cg.shared.global [%0], [%1], 16;" :: "r"(dst), "l"(src) : "memory")
#define CP_COMMIT() asm volatile("cp.async.commit_group;" ::: "memory")
#define CP_WAIT0()  asm volatile("cp.async.wait_group 0;" ::: "memory")
#define CP_WAIT1()  asm volatile("cp.async.wait_group 1;" ::: "memory")

#define MMA16816(d, a, b0, b1)                                               \
    asm volatile("mma.sync.aligned.m16n8k16.row.col.f32.bf16.bf16.f32 "      \
        "{%0,%1,%2,%3}, {%4,%5,%6,%7}, {%8,%9}, {%0,%1,%2,%3};"              \
        : "+f"((d)[0]), "+f"((d)[1]), "+f"((d)[2]), "+f"((d)[3])             \
        : "r"((a)[0]), "r"((a)[1]), "r"((a)[2]), "r"((a)[3]),                \
          "r"(b0), "r"(b1))

// ldmatrix x4 (sm_75+ baseline PTX)
#define LDSM4(r0, r1, r2, r3, addr)                                          \
    asm volatile("ldmatrix.sync.aligned.m8n8.x4.shared.b16 {%0,%1,%2,%3}, [%4];" \
        : "=r"(r0), "=r"(r1), "=r"(r2), "=r"(r3) : "r"(addr))

__device__ __forceinline__ float ex2f(float x) {
    float r;
    asm("ex2.approx.ftz.f32 %0, %1;" : "=f"(r) : "f"(x));
    return r;
}

// ---------------- split helpers ----------------
__device__ __forceinline__ void split1(float x, bf16& h, bf16& l) {
    h = __float2bfloat16(x);
    l = __float2bfloat16(x - __bfloat162float(h));
}
__device__ __forceinline__ uint32_t packbf(float a, float b) {
    __nv_bfloat162 p = __floats2bfloat162_rn(a, b);
    return *reinterpret_cast<uint32_t*>(&p);
}
__device__ __forceinline__ void split2(float a, float b, uint32_t& hp, uint32_t& lp) {
    hp = packbf(a, b);
    __nv_bfloat162 hh = *reinterpret_cast<__nv_bfloat162*>(&hp);
    lp = packbf(a - __bfloat162float(hh.x), b - __bfloat162float(hh.y));
}

// ldmatrix lane-address components.
struct LaneAddr {
    int rA, cA, rB, cB;
    __device__ __forceinline__ LaneAddr(int lane) {
        rA = (lane & 7) + ((lane >> 3) & 1) * 8;
        cA = (lane >> 4) * 8;
        rB = (lane & 7) + ((lane >> 4) & 1) * 8;
        cB = ((lane >> 3) & 1) * 8;
    }
};

// ---------------- HMMA bf16-split GEMM (BK=32, 2 CTAs/SM) ----------------
// C = (Ah+Al)(Bh+Bl)^T (+bias)(+resid)(relu); SPLIT: write bf16 hi/lo.
template<bool BIAS, bool RES, bool RELU, bool SPLIT>
__global__ __launch_bounds__(256, 2)
void mma_gemm(const bf16* __restrict__ Ah, const bf16* __restrict__ Al,
              const bf16* __restrict__ Bh, const bf16* __restrict__ Bl,
              const float* __restrict__ bias, const float* __restrict__ resid,
              float* __restrict__ C, bf16* __restrict__ Ch, bf16* __restrict__ Cl,
              int K, int lda, int ldb, int ldc, int ldres)
{
    constexpr int BM = 128, BN = 128, BK = 32;
    constexpr int SROW   = BK + 8;               // 40 halves (80 B rows)
    constexpr int A_TILE = BM * SROW;
    constexpr int B_TILE = BN * SROW;
    constexpr int STAGE  = 2 * A_TILE + 2 * B_TILE;
    constexpr int NT     = 8;

    extern __shared__ __align__(16) bf16 smem[];
    const uint32_t sbase = smem_u32(smem);
    const int tid = threadIdx.x;

    const int row0 = blockIdx.y * BM;
    const int col0 = blockIdx.x * BN;

    const int wid = tid >> 5, lane = tid & 31;
    const int g = lane >> 2, t = lane & 3;
    const int wrow0 = (wid & 3) * 32;
    const int wcol0 = (wid >> 2) * 64;
    const LaneAddr la(lane);

    float acc[2][NT][4];
    #pragma unroll
    for (int mt = 0; mt < 2; mt++)
        #pragma unroll
        for (int nt = 0; nt < NT; nt++)
            #pragma unroll
            for (int i = 0; i < 4; i++) acc[mt][nt][i] = 0.f;

    auto stage = [&](int b, int c) {
        const int k0 = c * BK;
        const uint32_t sb = sbase + (uint32_t)b * STAGE * 2;
        #pragma unroll
        for (int i = tid; i < BM * 4; i += 256) {
            int r = i >> 2, q = i & 3;
            uint32_t d = sb + (uint32_t)(r * SROW + q * 8) * 2;
            size_t gofs = (size_t)(row0 + r) * lda + k0 + q * 8;
            CP16(d, Ah + gofs);
            CP16(d + A_TILE * 2, Al + gofs);
        }
        #pragma unroll
        for (int i = tid; i < BN * 4; i += 256) {
            int r = i >> 2, q = i & 3;
            uint32_t d = sb + (uint32_t)(2 * A_TILE + r * SROW + q * 8) * 2;
            size_t gofs = (size_t)(col0 + r) * ldb + k0 + q * 8;
            CP16(d, Bh + gofs);
            CP16(d + B_TILE * 2, Bl + gofs);
        }
    };

    const int NC = K / BK;
    stage(0, 0);
    CP_COMMIT();

    for (int c = 0; c < NC; c++) {
        if (c + 1 < NC) { stage((c + 1) & 1, c + 1); CP_COMMIT(); CP_WAIT1(); }
        else            { CP_WAIT0(); }
        __syncthreads();

        const uint32_t bufb = sbase + (uint32_t)(c & 1) * STAGE * 2;
        const uint32_t aA = bufb + (uint32_t)((wrow0 + la.rA) * SROW + la.cA) * 2;
        const uint32_t aB = bufb + 2 * A_TILE * 2
                          + (uint32_t)((wcol0 + la.rB) * SROW + la.cB) * 2;

        #pragma unroll
        for (int ks = 0; ks < BK / 16; ks++) {
            const uint32_t kk2 = (uint32_t)ks * 32;     // 16 halves
            uint32_t ah[2][4], al[2][4];
            #pragma unroll
            for (int mt = 0; mt < 2; mt++) {
                uint32_t ab = aA + (uint32_t)mt * (16 * SROW * 2) + kk2;
                LDSM4(ah[mt][0], ah[mt][1], ah[mt][2], ah[mt][3], ab);
                LDSM4(al[mt][0], al[mt][1], al[mt][2], al[mt][3], ab + A_TILE * 2);
            }
            #pragma unroll
            for (int ntp = 0; ntp < 4; ntp++) {
                uint32_t bb = aB + (uint32_t)ntp * (16 * SROW * 2) + kk2;
                uint32_t h0a, h1a, h0b, h1b, l0a, l1a, l0b, l1b;
                LDSM4(h0a, h1a, h0b, h1b, bb);
                LDSM4(l0a, l1a, l0b, l1b, bb + B_TILE * 2);
                #pragma unroll
                for (int mt = 0; mt < 2; mt++) {
                    MMA16816(acc[mt][2*ntp],   ah[mt], h0a, h1a);
                    MMA16816(acc[mt][2*ntp],   ah[mt], l0a, l1a);
                    MMA16816(acc[mt][2*ntp],   al[mt], h0a, h1a);
                    MMA16816(acc[mt][2*ntp+1], ah[mt], h0b, h1b);
                    MMA16816(acc[mt][2*ntp+1], ah[mt], l0b, l1b);
                    MMA16816(acc[mt][2*ntp+1], al[mt], h0b, h1b);
                }
            }
        }
        __syncthreads();
    }

    #pragma unroll
    for (int mt = 0; mt < 2; mt++) {
        const int r = row0 + wrow0 + mt * 16 + g;
        #pragma unroll
        for (int nt = 0; nt < NT; nt++) {
            const int n = col0 + wcol0 + nt * 8 + t * 2;
            float v0 = acc[mt][nt][0];
            float v1 = acc[mt][nt][1];
            float v2 = acc[mt][nt][2];
            float v3 = acc[mt][nt][3];
            if (BIAS) { v0 += bias[n]; v1 += bias[n + 1]; v2 += bias[n]; v3 += bias[n + 1]; }
            if (RES) {
                v0 += resid[(size_t)r * ldres + n];
                v1 += resid[(size_t)r * ldres + n + 1];
                v2 += resid[(size_t)(r + 8) * ldres + n];
                v3 += resid[(size_t)(r + 8) * ldres + n + 1];
            }
            if (RELU) {
                v0 = fmaxf(v0, 0.f); v1 = fmaxf(v1, 0.f);
                v2 = fmaxf(v2, 0.f); v3 = fmaxf(v3, 0.f);
            }
            if (SPLIT) {
                uint32_t hp, lp;
                split2(v0, v1, hp, lp);
                *(uint32_t*)&Ch[(size_t)r * ldc + n] = hp;
                *(uint32_t*)&Cl[(size_t)r * ldc + n] = lp;
                split2(v2, v3, hp, lp);
                *(uint32_t*)&Ch[(size_t)(r + 8) * ldc + n] = hp;
                *(uint32_t*)&Cl[(size_t)(r + 8) * ldc + n] = lp;
            } else {
                *(float2*)&C[(size_t)r * ldc + n]       = make_float2(v0, v1);
                *(float2*)&C[(size_t)(r + 8) * ldc + n] = make_float2(v2, v3);
            }
        }
    }
}

// ---------------- Flash attention: KV-tile 64, 2 CTAs/SM ----------------
// Q pre-scaled by 0.125*log2(e). out written as bf16 hi/lo into [b*S, h*64+d].
// smem: Q 128x72 h+l (36864B) | K 2buf x 64x72 h+l (36864B) | V 2buf x 64x72 h+l (36864B)
__global__ __launch_bounds__(256, 2)
void flash_attn(const bf16* __restrict__ qh, const bf16* __restrict__ ql,
                const bf16* __restrict__ kh, const bf16* __restrict__ kl,
                const bf16* __restrict__ vh, const bf16* __restrict__ vl,
                bf16* __restrict__ outh, bf16* __restrict__ outl)
{
    constexpr int QL_OFF  = 128 * 72;             // 9216 halves
    constexpr int KST_OFF = 2 * 128 * 72;         // 18432
    constexpr int KBUF    = 2 * 64 * 72;          // 9216 halves (hi+lo)
    constexpr int KLO     = 64 * 72;              // 4608
    constexpr int VST_OFF = KST_OFF + 2 * KBUF;   // 36864
    constexpr int VBUF    = 2 * 64 * 72;          // 9216
    constexpr int VLO     = 64 * 72;              // 4608

    extern __shared__ __align__(16) bf16 smem[];
    const uint32_t sb = smem_u32(smem);
    const int tid = threadIdx.x;
    const int z = blockIdx.y, zb = z >> 4, zh = z & 15;
    const int q0 = blockIdx.x * 128;

    const bf16* Qh = qh + (size_t)z * SEQ * HD;
    const bf16* Ql = ql + (size_t)z * SEQ * HD;
    const bf16* Kh = kh + (size_t)z * SEQ * HD;
    const bf16* Kl = kl + (size_t)z * SEQ * HD;
    const bf16* Vh = vh + (size_t)z * HD * SEQ;
    const bf16* Vl = vl + (size_t)z * HD * SEQ;

    auto stage_kv = [&](int b, int j) {
        const int s0 = j * 64;
        // K tile: 64 rows x 64 cols = 512 8-half chunks
        const uint32_t kb = sb + (uint32_t)(KST_OFF + b * KBUF) * 2;
        #pragma unroll
        for (int i = tid; i < 512; i += 256) {
            int r = i >> 3, q = i & 7;
            uint32_t d = kb + (uint32_t)(r * 72 + q * 8) * 2;
            size_t gofs = (size_t)(s0 + r) * HD + q * 8;
            CP16(d, Kh + gofs);
            CP16(d + KLO * 2, Kl + gofs);
        }
        // V tile: 64 d-rows x 64 s-cols = 512 chunks
        const uint32_t vb = sb + (uint32_t)(VST_OFF + b * VBUF) * 2;
        #pragma unroll
        for (int i = tid; i < 512; i += 256) {
            int r = i >> 3, q = i & 7;
            uint32_t d = vb + (uint32_t)(r * 72 + q * 8) * 2;
            size_t gofs = (size_t)r * SEQ + s0 + q * 8;
            CP16(d, Vh + gofs);
            CP16(d + VLO * 2, Vl + gofs);
        }
    };

    // stage Q (once) + first K/V tile in one group
    for (int i = tid; i < 1024; i += 256) {
        int r = i >> 3, c = i & 7;
        uint32_t d = sb + (uint32_t)(r * 72 + c * 8) * 2;
        size_t gofs = (size_t)(q0 + r) * HD + c * 8;
        CP16(d, Qh + gofs);
        CP16(d + QL_OFF * 2, Ql + gofs);
    }
    stage_kv(0, 0);
    CP_COMMIT();

    const int wid = tid >> 5, lane = tid & 31;
    const int g = lane >> 2, t = lane & 3;
    const int wq = wid * 16;
    const LaneAddr la(lane);

    float o[8][4];
    #pragma unroll
    for (int nt = 0; nt < 8; nt++)
        #pragma unroll
        for (int i = 0; i < 4; i++) o[nt][i] = 0.f;
    float m0 = -1e30f, m1 = -1e30f, l0 = 0.f, l1 = 0.f;

    const uint32_t aQ = sb + (uint32_t)((wq + la.rA) * 72 + la.cA) * 2;

    const int NJ = SEQ / 64;   // 32
    for (int j = 0; j < NJ; j++) {
        const int b = j & 1;
        if (j + 1 < NJ) { stage_kv(b ^ 1, j + 1); CP_COMMIT(); CP_WAIT1(); }
        else            { CP_WAIT0(); }
        __syncthreads();

        const uint32_t kbase = sb + (uint32_t)(KST_OFF + b * KBUF) * 2
                             + (uint32_t)(la.rB * 72 + la.cB) * 2;
        const uint32_t vbase = sb + (uint32_t)(VST_OFF + b * VBUF) * 2
                             + (uint32_t)(la.rB * 72 + la.cB) * 2;

        // ---- S = Q @ K^T over 64 kv cols (log2 domain) ----
        float s[8][4];
        #pragma unroll
        for (int nt = 0; nt < 8; nt++)
            #pragma unroll
            for (int i = 0; i < 4; i++) s[nt][i] = 0.f;

        #pragma unroll
        for (int ks = 0; ks < 4; ks++) {
            const uint32_t kk2 = (uint32_t)ks * 32;
            uint32_t ah[4], al[4];
            LDSM4(ah[0], ah[1], ah[2], ah[3], aQ + kk2);
            LDSM4(al[0], al[1], al[2], al[3], aQ + kk2 + QL_OFF * 2);
            #pragma unroll
            for (int ntp = 0; ntp < 4; ntp++) {
                uint32_t bb = kbase + (uint32_t)ntp * (16 * 72 * 2) + kk2;
                uint32_t h0a, h1a, h0b, h1b, l0a, l1a, l0b, l1b;
                LDSM4(h0a, h1a, h0b, h1b, bb);
                LDSM4(l0a, l1a, l0b, l1b, bb + KLO * 2);
                MMA16816(s[2*ntp],   ah, h0a, h1a);
                MMA16816(s[2*ntp],   ah, l0a, l1a);
                MMA16816(s[2*ntp],   al, h0a, h1a);
                MMA16816(s[2*ntp+1], ah, h0b, h1b);
                MMA16816(s[2*ntp+1], ah, l0b, l1b);
                MMA16816(s[2*ntp+1], al, h0b, h1b);
            }
        }

        // ---- online softmax (rows g and g+8) ----
        float tm0 = -1e30f, tm1 = -1e30f;
        #pragma unroll
        for (int nt = 0; nt < 8; nt++) {
            tm0 = fmaxf(tm0, fmaxf(s[nt][0], s[nt][1]));
            tm1 = fmaxf(tm1, fmaxf(s[nt][2], s[nt][3]));
        }
        tm0 = fmaxf(tm0, __shfl_xor_sync(0xffffffffu, tm0, 1));
        tm0 = fmaxf(tm0, __shfl_xor_sync(0xffffffffu, tm0, 2));
        tm1 = fmaxf(tm1, __shfl_xor_sync(0xffffffffu, tm1, 1));
        tm1 = fmaxf(tm1, __shfl_xor_sync(0xffffffffu, tm1, 2));
        const float mn0 = fmaxf(m0, tm0), mn1 = fmaxf(m1, tm1);
        const float f0 = ex2f(m0 - mn0), f1 = ex2f(m1 - mn1);
        float sum0 = 0.f, sum1 = 0.f;
        #pragma unroll
        for (int nt = 0; nt < 8; nt++) {
            s[nt][0] = ex2f(s[nt][0] - mn0);
            s[nt][1] = ex2f(s[nt][1] - mn0);
            s[nt][2] = ex2f(s[nt][2] - mn1);
            s[nt][3] = ex2f(s[nt][3] - mn1);
            sum0 += s[nt][0] + s[nt][1];
            sum1 += s[nt][2] + s[nt][3];
        }
        sum0 += __shfl_xor_sync(0xffffffffu, sum0, 1);
        sum0 += __shfl_xor_sync(0xffffffffu, sum0, 2);
        sum1 += __shfl_xor_sync(0xffffffffu, sum1, 1);
        sum1 += __shfl_xor_sync(0xffffffffu, sum1, 2);
        l0 = l0 * f0 + sum0;  l1 = l1 * f1 + sum1;
        m0 = mn0;  m1 = mn1;
        #pragma unroll
        for (int nt = 0; nt < 8; nt++) {
            o[nt][0] *= f0; o[nt][1] *= f0;
            o[nt][2] *= f1; o[nt][3] *= f1;
        }

        // ---- O += P @ V (P split built from S fragments) ----
        #pragma unroll
        for (int kc = 0; kc < 4; kc++) {
            uint32_t ph[4], pl[4];
            split2(s[2*kc][0],   s[2*kc][1],   ph[0], pl[0]);
            split2(s[2*kc][2],   s[2*kc][3],   ph[1], pl[1]);
            split2(s[2*kc+1][0], s[2*kc+1][1], ph[2], pl[2]);
            split2(s[2*kc+1][2], s[2*kc+1][3], ph[3], pl[3]);
            const uint32_t kk2 = (uint32_t)kc * 32;
            #pragma unroll
            for (int ntp = 0; ntp < 4; ntp++) {
                uint32_t bb = vbase + (uint32_t)ntp * (16 * 72 * 2) + kk2;
                uint32_t h0a, h1a, h0b, h1b, l0a, l1a, l0b, l1b;
                LDSM4(h0a, h1a, h0b, h1b, bb);
                LDSM4(l0a, l1a, l0b, l1b, bb + VLO * 2);
                MMA16816(o[2*ntp],   ph, h0a, h1a);
                MMA16816(o[2*ntp],   ph, l0a, l1a);
                MMA16816(o[2*ntp],   pl, h0a, h1a);
                MMA16816(o[2*ntp+1], ph, h0b, h1b);
                MMA16816(o[2*ntp+1], ph, l0b, l1b);
                MMA16816(o[2*ntp+1], pl, h0b, h1b);
            }
        }
        __syncthreads();
    }

    // ---- normalize + write bf16 hi/lo ----
    const float i0 = 1.f / l0, i1 = 1.f / l1;
    const int row = zb * SEQ + q0 + wq + g;
    #pragma unroll
    for (int nt = 0; nt < 8; nt++) {
        const int col = zh * 64 + nt * 8 + t * 2;
        uint32_t hp, lp;
        split2(o[nt][0] * i0, o[nt][1] * i0, hp, lp);
        *(uint32_t*)&outh[(size_t)row * EMBED + col] = hp;
        *(uint32_t*)&outl[(size_t)row * EMBED + col] = lp;
        split2(o[nt][2] * i1, o[nt][3] * i1, hp, lp);
        *(uint32_t*)&outh[(size_t)(row + 8) * EMBED + col] = hp;
        *(uint32_t*)&outl[(size_t)(row + 8) * EMBED + col] = lp;
    }
}

// ---------------- LayerNorm -> bf16 hi/lo ----------------
__global__ void ln_split(const float* __restrict__ x,
                         const float* __restrict__ gam,
                         const float* __restrict__ bet,
                         bf16* __restrict__ hi, bf16* __restrict__ lo) {
    int row = blockIdx.x;
    int t = threadIdx.x;
    const float4* xr = (const float4*)(x + (size_t)row * EMBED);
    float4 v = xr[t];
    float s  = v.x + v.y + v.z + v.w;
    float ss = v.x*v.x + v.y*v.y + v.z*v.z + v.w*v.w;
    #pragma unroll
    for (int o = 16; o; o >>= 1) {
        s  += __shfl_xor_sync(0xffffffffu, s,  o);
        ss += __shfl_xor_sync(0xffffffffu, ss, o);
    }
    __shared__ float shs[8], shs2[8];
    int w = t >> 5;
    if ((t & 31) == 0) { shs[w] = s; shs2[w] = ss; }
    __syncthreads();
    float tot = 0.f, tot2 = 0.f;
    #pragma unroll
    for (int i = 0; i < 8; i++) { tot += shs[i]; tot2 += shs2[i]; }
    float mu  = tot * (1.f / EMBED);
    float var = tot2 * (1.f / EMBED) - mu * mu;
    float rs  = rsqrtf(var + 1e-5f);
    float4 gv = ((const float4*)gam)[t];
    float4 bv = ((const float4*)bet)[t];
    float o0 = (v.x - mu) * rs * gv.x + bv.x;
    float o1 = (v.y - mu) * rs * gv.y + bv.y;
    float o2 = (v.z - mu) * rs * gv.z + bv.z;
    float o3 = (v.w - mu) * rs * gv.w + bv.w;
    uint32_t hp, lp;
    size_t base = (size_t)row * EMBED + t * 4;
    split2(o0, o1, hp, lp);
    *(uint32_t*)&hi[base] = hp;  *(uint32_t*)&lo[base] = lp;
    split2(o2, o3, hp, lp);
    *(uint32_t*)&hi[base + 2] = hp;  *(uint32_t*)&lo[base + 2] = lp;
}

// ---------------- conversions ----------------
// qkv [b,s,3072] -> q[z,s,d]*(0.125*log2e) and k[z,s,d]
__global__ void conv_qk(const float* __restrict__ qkv,
                        bf16* __restrict__ qh, bf16* __restrict__ ql,
                        bf16* __restrict__ kh, bf16* __restrict__ kl) {
    const float SCL = 0.125f * 1.4426950408889634f;
    size_t idx = (size_t)blockIdx.x * 256 + threadIdx.x;
    int d = idx & 63;
    int s = (idx >> 6) & 2047;
    int z = idx >> 17;
    int zb = z >> 4, zh = z & 15;
    size_t src = ((size_t)(zb * 2048 + s)) * QKVN + zh * 64 + d;
    bf16 h, l;
    split1(qkv[src] * SCL, h, l);   qh[idx] = h; ql[idx] = l;
    split1(qkv[src + 1024], h, l);  kh[idx] = h; kl[idx] = l;
}

// qkv V -> vT[z,d,s]
__global__ void conv_vT(const float* __restrict__ qkv,
                        bf16* __restrict__ vh, bf16* __restrict__ vl) {
    size_t idx = (size_t)blockIdx.x * 256 + threadIdx.x;
    int s = idx & 2047;
    int d = (idx >> 11) & 63;
    int z = idx >> 17;
    int zb = z >> 4, zh = z & 15;
    size_t src = ((size_t)(zb * 2048 + s)) * QKVN + 2048 + zh * 64 + d;
    bf16 h, l;
    split1(qkv[src], h, l);
    vh[idx] = h; vl[idx] = l;
}

// tiled transpose + split
__global__ void conv_T(const float* __restrict__ in,
                       bf16* __restrict__ hi, bf16* __restrict__ lo,
                       int K, int N, long inz, long outz) {
    __shared__ float t[32][33];
    in += (size_t)blockIdx.z * inz;
    hi += (size_t)blockIdx.z * outz;
    lo += (size_t)blockIdx.z * outz;
    int n0 = blockIdx.x * 32, k0 = blockIdx.y * 32;
    int tx = threadIdx.x, ty = threadIdx.y;    // (32, 8)
    #pragma unroll
    for (int j = 0; j < 32; j += 8)
        t[ty + j][tx] = in[(size_t)(k0 + ty + j) * N + n0 + tx];
    __syncthreads();
    #pragma unroll
    for (int j = 0; j < 32; j += 8) {
        float v = t[tx][ty + j];
        bf16 h, l; split1(v, h, l);
        size_t o = (size_t)(n0 + ty + j) * K + k0 + tx;
        hi[o] = h; lo[o] = l;
    }
}

// ---------------- launch ----------------
extern "C" void kernel_launch(void* const* d_in, const int* in_sizes, int n_in,
                              void* d_out, int out_size) {
    const float* x    = (const float*)d_in[0];
    const float* Wqkv = (const float*)d_in[1];
    const float* bqkv = (const float*)d_in[2];
    const float* Wo   = (const float*)d_in[3];
    const float* bo   = (const float*)d_in[4];
    const float* W1   = (const float*)d_in[5];
    const float* b1   = (const float*)d_in[6];
    const float* W2   = (const float*)d_in[7];
    const float* b2   = (const float*)d_in[8];
    const float* g1   = (const float*)d_in[9];
    const float* be1  = (const float*)d_in[10];
    const float* g2   = (const float*)d_in[11];
    const float* be2  = (const float*)d_in[12];
    float* out = (float*)d_out;

    float *qkv, *x2;
    cudaGetSymbolAddress((void**)&qkv, g_qkv);
    cudaGetSymbolAddress((void**)&x2,  g_x2);

    bf16 *nrm_h,*nrm_l,*wqkvT_h,*wqkvT_l,*q_h,*q_l,*k_h,*k_l,*vT_h,*vT_l;
    bf16 *attn_h,*attn_l,*woT_h,*woT_l,*n2_h,*n2_l;
    bf16 *w1T_h,*w1T_l,*ff1_h,*ff1_l,*w2T_h,*w2T_l;
    cudaGetSymbolAddress((void**)&nrm_h,   g_nrm_h);   cudaGetSymbolAddress((void**)&nrm_l,   g_nrm_l);
    cudaGetSymbolAddress((void**)&wqkvT_h, g_wqkvT_h); cudaGetSymbolAddress((void**)&wqkvT_l, g_wqkvT_l);
    cudaGetSymbolAddress((void**)&q_h,     g_q_h);     cudaGetSymbolAddress((void**)&q_l,     g_q_l);
    cudaGetSymbolAddress((void**)&k_h,     g_k_h);     cudaGetSymbolAddress((void**)&k_l,     g_k_l);
    cudaGetSymbolAddress((void**)&vT_h,    g_vT_h);    cudaGetSymbolAddress((void**)&vT_l,    g_vT_l);
    cudaGetSymbolAddress((void**)&attn_h,  g_attn_h);  cudaGetSymbolAddress((void**)&attn_l,  g_attn_l);
    cudaGetSymbolAddress((void**)&woT_h,   g_woT_h);   cudaGetSymbolAddress((void**)&woT_l,   g_woT_l);
    cudaGetSymbolAddress((void**)&n2_h,    g_n2_h);    cudaGetSymbolAddress((void**)&n2_l,    g_n2_l);
    cudaGetSymbolAddress((void**)&w1T_h,   g_w1T_h);   cudaGetSymbolAddress((void**)&w1T_l,   g_w1T_l);
    cudaGetSymbolAddress((void**)&ff1_h,   g_ff1_h);   cudaGetSymbolAddress((void**)&ff1_l,   g_ff1_l);
    cudaGetSymbolAddress((void**)&w2T_h,   g_w2T_h);   cudaGetSymbolAddress((void**)&w2T_l,   g_w2T_l);

    const int SMGEMM = 2 * (2*128 + 2*128) * 40 * 2;   // 81920 (2 CTAs/SM)
    const int SMFA   = (2*128*72 + 2*(2*64*72) + 2*(2*64*72)) * 2;  // 110592 (2 CTAs/SM)
    cudaFuncSetAttribute(mma_gemm<true,false,false,false>, cudaFuncAttributeMaxDynamicSharedMemorySize, SMGEMM);
    cudaFuncSetAttribute(mma_gemm<true,true, false,false>, cudaFuncAttributeMaxDynamicSharedMemorySize, SMGEMM);
    cudaFuncSetAttribute(mma_gemm<true,false,true, true >, cudaFuncAttributeMaxDynamicSharedMemorySize, SMGEMM);
    cudaFuncSetAttribute(flash_attn, cudaFuncAttributeMaxDynamicSharedMemorySize, SMFA);

    dim3 tblk(32, 8);

    // launch order arranged so the ncu-captured slot (4th launch) is the QKV GEMM
    // 1) Wqkv transpose+split
    conv_T<<<dim3(2, 32, 48), tblk>>>(Wqkv, wqkvT_h, wqkvT_l, EMBED, HD, 65536, 65536);
    // 2) LN1 -> split
    ln_split<<<MTOK, 256>>>(x, g1, be1, nrm_h, nrm_l);
    // 3) Wo transpose+split
    conv_T<<<dim3(32, 32, 1), tblk>>>(Wo, woT_h, woT_l, EMBED, EMBED, 0, 0);
    // 4) QKV projection -> fp32 qkv (+bias)   <-- profiled slot
    mma_gemm<true,false,false,false><<<dim3(QKVN/128, MTOK/128), 256, SMGEMM>>>(
        nrm_h, nrm_l, wqkvT_h, wqkvT_l, bqkv, nullptr, qkv, nullptr, nullptr,
        EMBED, EMBED, EMBED, QKVN, 0);
    // 5-6) split Q (scaled), K, V^T
    conv_qk<<<(32*SEQ*HD)/256, 256>>>(qkv, q_h, q_l, k_h, k_l);
    conv_vT<<<(32*HD*SEQ)/256, 256>>>(qkv, vT_h, vT_l);
    // 7) fused attention -> attn hi/lo
    flash_attn<<<dim3(SEQ/128, 32), 256, SMFA>>>(
        q_h, q_l, k_h, k_l, vT_h, vT_l, attn_h, attn_l);
    // 8) O projection + bias + residual(x) -> x2
    mma_gemm<true,true,false,false><<<dim3(EMBED/128, MTOK/128), 256, SMGEMM>>>(
        attn_h, attn_l, woT_h, woT_l, bo, x, x2, nullptr, nullptr,
        EMBED, EMBED, EMBED, EMBED, EMBED);
    // 9) LN2 -> split
    ln_split<<<MTOK, 256>>>(x2, g2, be2, n2_h, n2_l);
    // 10) W1 transpose+split
    conv_T<<<dim3(128,32, 1), tblk>>>(W1, w1T_h, w1T_l, EMBED, FF, 0, 0);
    // 11) FF1 + bias + relu -> ff1 hi/lo
    mma_gemm<true,false,true,true><<<dim3(FF/128, MTOK/128), 256, SMGEMM>>>(
        n2_h, n2_l, w1T_h, w1T_l, b1, nullptr, nullptr, ff1_h, ff1_l,
        EMBED, EMBED, EMBED, FF, 0);
    // 12) W2 transpose+split
    conv_T<<<dim3(32,128, 1), tblk>>>(W2, w2T_h, w2T_l, FF, EMBED, 0, 0);
    // 13) FF2 + bias + residual(x2) -> out
    mma_gemm<true,true,false,false><<<dim3(EMBED/128, MTOK/128), 256, SMGEMM>>>(
        ff1_h, ff1_l, w2T_h, w2T_l, b2, x2, out, nullptr, nullptr,
        FF, FF, FF, EMBED, EMBED);
}

// round 17
// speedup vs baseline: 1.5425x; 1.5425x over previous
#include <cuda_runtime.h>
#include <cuda_bf16.h>
#include <cstdint>
#include <math.h>

// ---------------- problem constants ----------------
#define BATCH 2
#define SEQ   2048
#define EMBED 1024
#define HEADS 16
#define HD    64
#define FF    4096
#define MTOK  (BATCH*SEQ)          // 4096
#define QKVN  (3*EMBED)            // 3072

typedef __nv_bfloat16 bf16;

// ---------------- device scratch ----------------
__device__ __align__(16) float g_qkv    [(size_t)MTOK*QKVN];
__device__ __align__(16) float g_x2     [(size_t)MTOK*EMBED];

__device__ __align__(16) bf16 g_nrm_h  [(size_t)MTOK*EMBED];
__device__ __align__(16) bf16 g_nrm_l  [(size_t)MTOK*EMBED];
__device__ __align__(16) bf16 g_wqkvT_h[(size_t)QKVN*EMBED];
__device__ __align__(16) bf16 g_wqkvT_l[(size_t)QKVN*EMBED];
__device__ __align__(16) bf16 g_q_h    [(size_t)BATCH*HEADS*SEQ*HD];
__device__ __align__(16) bf16 g_q_l    [(size_t)BATCH*HEADS*SEQ*HD];
__device__ __align__(16) bf16 g_k_h    [(size_t)BATCH*HEADS*SEQ*HD];
__device__ __align__(16) bf16 g_k_l    [(size_t)BATCH*HEADS*SEQ*HD];
__device__ __align__(16) bf16 g_vT_h   [(size_t)BATCH*HEADS*HD*SEQ];
__device__ __align__(16) bf16 g_vT_l   [(size_t)BATCH*HEADS*HD*SEQ];
__device__ __align__(16) bf16 g_attn_h [(size_t)MTOK*EMBED];
__device__ __align__(16) bf16 g_attn_l [(size_t)MTOK*EMBED];
__device__ __align__(16) bf16 g_woT_h  [(size_t)EMBED*EMBED];
__device__ __align__(16) bf16 g_woT_l  [(size_t)EMBED*EMBED];
__device__ __align__(16) bf16 g_n2_h   [(size_t)MTOK*EMBED];
__device__ __align__(16) bf16 g_n2_l   [(size_t)MTOK*EMBED];
__device__ __align__(16) bf16 g_w1T_h  [(size_t)FF*EMBED];
__device__ __align__(16) bf16 g_w1T_l  [(size_t)FF*EMBED];
__device__ __align__(16) bf16 g_ff1_h  [(size_t)MTOK*FF];
__device__ __align__(16) bf16 g_ff1_l  [(size_t)MTOK*FF];
__device__ __align__(16) bf16 g_w2T_h  [(size_t)EMBED*FF];
__device__ __align__(16) bf16 g_w2T_l  [(size_t)EMBED*FF];

// ---------------- PTX helpers (sm_80-level baseline only) ----------------
__device__ __forceinline__ uint32_t smem_u32(const void* p) {
    uint32_t a;
    asm("{ .reg .u64 t; cvta.to.shared.u64 t, %1; cvt.u32.u64 %0, t; }" : "=r"(a) : "l"(p));
    return a;
}
#define CP16(dst, src) \
    asm volatile("cp.async.cg.shared.global [%0], [%1], 16;" :: "r"(dst), "l"(src) : "memory")
#define CP_COMMIT() asm volatile("cp.async.commit_group;" ::: "memory")
#define CP_WAIT0()  asm volatile("cp.async.wait_group 0;" ::: "memory")
#define CP_WAIT1()  asm volatile("cp.async.wait_group 1;" ::: "memory")

#define MMA16816(d, a, b0, b1)                                               \
    asm volatile("mma.sync.aligned.m16n8k16.row.col.f32.bf16.bf16.f32 "      \
        "{%0,%1,%2,%3}, {%4,%5,%6,%7}, {%8,%9}, {%0,%1,%2,%3};"              \
        : "+f"((d)[0]), "+f"((d)[1]), "+f"((d)[2]), "+f"((d)[3])             \
        : "r"((a)[0]), "r"((a)[1]), "r"((a)[2]), "r"((a)[3]),                \
          "r"(b0), "r"(b1))

// ldmatrix x4 (sm_75+ baseline PTX)
#define LDSM4(r0, r1, r2, r3, addr)                                          \
    asm volatile("ldmatrix.sync.aligned.m8n8.x4.shared.b16 {%0,%1,%2,%3}, [%4];" \
        : "=r"(r0), "=r"(r1), "=r"(r2), "=r"(r3) : "r"(addr))

__device__ __forceinline__ float ex2f(float x) {
    float r;
    asm("ex2.approx.ftz.f32 %0, %1;" : "=f"(r) : "f"(x));
    return r;
}

// ---------------- split helpers ----------------
__device__ __forceinline__ void split1(float x, bf16& h, bf16& l) {
    h = __float2bfloat16(x);
    l = __float2bfloat16(x - __bfloat162float(h));
}
__device__ __forceinline__ uint32_t packbf(float a, float b) {
    __nv_bfloat162 p = __floats2bfloat162_rn(a, b);
    return *reinterpret_cast<uint32_t*>(&p);
}
__device__ __forceinline__ void split2(float a, float b, uint32_t& hp, uint32_t& lp) {
    hp = packbf(a, b);
    __nv_bfloat162 hh = *reinterpret_cast<__nv_bfloat162*>(&hp);
    lp = packbf(a - __bfloat162float(hh.x), b - __bfloat162float(hh.y));
}

// ldmatrix lane-address components.
struct LaneAddr {
    int rA, cA, rB, cB;
    __device__ __forceinline__ LaneAddr(int lane) {
        rA = (lane & 7) + ((lane >> 3) & 1) * 8;
        cA = (lane >> 4) * 8;
        rB = (lane & 7) + ((lane >> 4) & 1) * 8;
        cB = ((lane >> 3) & 1) * 8;
    }
};

// ---------------- HMMA bf16-split GEMM (BK=32, 2 CTAs/SM) ----------------
// C = (Ah+Al)(Bh+Bl)^T (+bias)(+resid)(relu); SPLIT: write bf16 hi/lo.
template<bool BIAS, bool RES, bool RELU, bool SPLIT>
__global__ __launch_bounds__(256, 2)
void mma_gemm(const bf16* __restrict__ Ah, const bf16* __restrict__ Al,
              const bf16* __restrict__ Bh, const bf16* __restrict__ Bl,
              const float* __restrict__ bias, const float* __restrict__ resid,
              float* __restrict__ C, bf16* __restrict__ Ch, bf16* __restrict__ Cl,
              int K, int lda, int ldb, int ldc, int ldres)
{
    constexpr int BM = 128, BN = 128, BK = 32;
    constexpr int SROW   = BK + 8;               // 40 halves (80 B rows)
    constexpr int A_TILE = BM * SROW;
    constexpr int B_TILE = BN * SROW;
    constexpr int STAGE  = 2 * A_TILE + 2 * B_TILE;
    constexpr int NT     = 8;

    extern __shared__ __align__(16) bf16 smem[];
    const uint32_t sbase = smem_u32(smem);
    const int tid = threadIdx.x;

    const int row0 = blockIdx.y * BM;
    const int col0 = blockIdx.x * BN;

    const int wid = tid >> 5, lane = tid & 31;
    const int g = lane >> 2, t = lane & 3;
    const int wrow0 = (wid & 3) * 32;
    const int wcol0 = (wid >> 2) * 64;
    const LaneAddr la(lane);

    float acc[2][NT][4];
    #pragma unroll
    for (int mt = 0; mt < 2; mt++)
        #pragma unroll
        for (int nt = 0; nt < NT; nt++)
            #pragma unroll
            for (int i = 0; i < 4; i++) acc[mt][nt][i] = 0.f;

    auto stage = [&](int b, int c) {
        const int k0 = c * BK;
        const uint32_t sb = sbase + (uint32_t)b * STAGE * 2;
        #pragma unroll
        for (int i = tid; i < BM * 4; i += 256) {
            int r = i >> 2, q = i & 3;
            uint32_t d = sb + (uint32_t)(r * SROW + q * 8) * 2;
            size_t gofs = (size_t)(row0 + r) * lda + k0 + q * 8;
            CP16(d, Ah + gofs);
            CP16(d + A_TILE * 2, Al + gofs);
        }
        #pragma unroll
        for (int i = tid; i < BN * 4; i += 256) {
            int r = i >> 2, q = i & 3;
            uint32_t d = sb + (uint32_t)(2 * A_TILE + r * SROW + q * 8) * 2;
            size_t gofs = (size_t)(col0 + r) * ldb + k0 + q * 8;
            CP16(d, Bh + gofs);
            CP16(d + B_TILE * 2, Bl + gofs);
        }
    };

    const int NC = K / BK;
    stage(0, 0);
    CP_COMMIT();

    for (int c = 0; c < NC; c++) {
        if (c + 1 < NC) { stage((c + 1) & 1, c + 1); CP_COMMIT(); CP_WAIT1(); }
        else            { CP_WAIT0(); }
        __syncthreads();

        const uint32_t bufb = sbase + (uint32_t)(c & 1) * STAGE * 2;
        const uint32_t aA = bufb + (uint32_t)((wrow0 + la.rA) * SROW + la.cA) * 2;
        const uint32_t aB = bufb + 2 * A_TILE * 2
                          + (uint32_t)((wcol0 + la.rB) * SROW + la.cB) * 2;

        #pragma unroll
        for (int ks = 0; ks < BK / 16; ks++) {
            const uint32_t kk2 = (uint32_t)ks * 32;     // 16 halves
            uint32_t ah[2][4], al[2][4];
            #pragma unroll
            for (int mt = 0; mt < 2; mt++) {
                uint32_t ab = aA + (uint32_t)mt * (16 * SROW * 2) + kk2;
                LDSM4(ah[mt][0], ah[mt][1], ah[mt][2], ah[mt][3], ab);
                LDSM4(al[mt][0], al[mt][1], al[mt][2], al[mt][3], ab + A_TILE * 2);
            }
            #pragma unroll
            for (int ntp = 0; ntp < 4; ntp++) {
                uint32_t bb = aB + (uint32_t)ntp * (16 * SROW * 2) + kk2;
                uint32_t h0a, h1a, h0b, h1b, l0a, l1a, l0b, l1b;
                LDSM4(h0a, h1a, h0b, h1b, bb);
                LDSM4(l0a, l1a, l0b, l1b, bb + B_TILE * 2);
                #pragma unroll
                for (int mt = 0; mt < 2; mt++) {
                    MMA16816(acc[mt][2*ntp],   ah[mt], h0a, h1a);
                    MMA16816(acc[mt][2*ntp],   ah[mt], l0a, l1a);
                    MMA16816(acc[mt][2*ntp],   al[mt], h0a, h1a);
                    MMA16816(acc[mt][2*ntp+1], ah[mt], h0b, h1b);
                    MMA16816(acc[mt][2*ntp+1], ah[mt], l0b, l1b);
                    MMA16816(acc[mt][2*ntp+1], al[mt], h0b, h1b);
                }
            }
        }
        __syncthreads();
    }

    #pragma unroll
    for (int mt = 0; mt < 2; mt++) {
        const int r = row0 + wrow0 + mt * 16 + g;
        #pragma unroll
        for (int nt = 0; nt < NT; nt++) {
            const int n = col0 + wcol0 + nt * 8 + t * 2;
            float v0 = acc[mt][nt][0];
            float v1 = acc[mt][nt][1];
            float v2 = acc[mt][nt][2];
            float v3 = acc[mt][nt][3];
            if (BIAS) { v0 += bias[n]; v1 += bias[n + 1]; v2 += bias[n]; v3 += bias[n + 1]; }
            if (RES) {
                v0 += resid[(size_t)r * ldres + n];
                v1 += resid[(size_t)r * ldres + n + 1];
                v2 += resid[(size_t)(r + 8) * ldres + n];
                v3 += resid[(size_t)(r + 8) * ldres + n + 1];
            }
            if (RELU) {
                v0 = fmaxf(v0, 0.f); v1 = fmaxf(v1, 0.f);
                v2 = fmaxf(v2, 0.f); v3 = fmaxf(v3, 0.f);
            }
            if (SPLIT) {
                uint32_t hp, lp;
                split2(v0, v1, hp, lp);
                *(uint32_t*)&Ch[(size_t)r * ldc + n] = hp;
                *(uint32_t*)&Cl[(size_t)r * ldc + n] = lp;
                split2(v2, v3, hp, lp);
                *(uint32_t*)&Ch[(size_t)(r + 8) * ldc + n] = hp;
                *(uint32_t*)&Cl[(size_t)(r + 8) * ldc + n] = lp;
            } else {
                *(float2*)&C[(size_t)r * ldc + n]       = make_float2(v0, v1);
                *(float2*)&C[(size_t)(r + 8) * ldc + n] = make_float2(v2, v3);
            }
        }
    }
}

// ---------------- Flash attention (per b,h; KV-tile 128, 1 CTA/SM) ----------------
// Q pre-scaled by 0.125*log2(e). out written as bf16 hi/lo into [b*S, h*64+d].
__global__ __launch_bounds__(256, 1)
void flash_attn(const bf16* __restrict__ qh, const bf16* __restrict__ ql,
                const bf16* __restrict__ kh, const bf16* __restrict__ kl,
                const bf16* __restrict__ vh, const bf16* __restrict__ vl,
                bf16* __restrict__ outh, bf16* __restrict__ outl)
{
    constexpr int QL_OFF  = 128 * 72;             // 9216 halves
    constexpr int KST_OFF = 2 * 128 * 72;         // 18432
    constexpr int KSTAGE  = 2 * 128 * 72;
    constexpr int VST_OFF = KST_OFF + 2 * KSTAGE; // 55296
    constexpr int VSTAGE  = 2 * 64 * 136;         // 17408 (272 B rows: conflict-free)

    extern __shared__ __align__(16) bf16 smem[];
    const uint32_t sb = smem_u32(smem);
    const int tid = threadIdx.x;
    const int z = blockIdx.y, zb = z >> 4, zh = z & 15;
    const int q0 = blockIdx.x * 128;

    const bf16* Qh = qh + (size_t)z * SEQ * HD;
    const bf16* Ql = ql + (size_t)z * SEQ * HD;
    const bf16* Kh = kh + (size_t)z * SEQ * HD;
    const bf16* Kl = kl + (size_t)z * SEQ * HD;
    const bf16* Vh = vh + (size_t)z * HD * SEQ;
    const bf16* Vl = vl + (size_t)z * HD * SEQ;

    auto stage_kv = [&](int b, int j) {
        const int s0 = j * 128;
        const uint32_t kb = sb + (uint32_t)(KST_OFF + b * KSTAGE) * 2;
        for (int i = tid; i < 1024; i += 256) {
            int r = i >> 3, c = i & 7;
            uint32_t d = kb + (uint32_t)(r * 72 + c * 8) * 2;
            size_t gofs = (size_t)(s0 + r) * HD + c * 8;
            CP16(d, Kh + gofs);
            CP16(d + 9216 * 2, Kl + gofs);
        }
        const uint32_t vb = sb + (uint32_t)(VST_OFF + b * VSTAGE) * 2;
        for (int i = tid; i < 1024; i += 256) {
            int r = i >> 4, c = i & 15;
            uint32_t d = vb + (uint32_t)(r * 136 + c * 8) * 2;
            size_t gofs = (size_t)r * SEQ + s0 + c * 8;
            CP16(d, Vh + gofs);
            CP16(d + 8704 * 2, Vl + gofs);
        }
    };

    // stage Q (once) + first K/V tile in one group
    for (int i = tid; i < 1024; i += 256) {
        int r = i >> 3, c = i & 7;
        uint32_t d = sb + (uint32_t)(r * 72 + c * 8) * 2;
        size_t gofs = (size_t)(q0 + r) * HD + c * 8;
        CP16(d, Qh + gofs);
        CP16(d + QL_OFF * 2, Ql + gofs);
    }
    stage_kv(0, 0);
    CP_COMMIT();

    const int wid = tid >> 5, lane = tid & 31;
    const int g = lane >> 2, t = lane & 3;
    const int wq = wid * 16;
    const LaneAddr la(lane);

    float o[8][4];
    #pragma unroll
    for (int nt = 0; nt < 8; nt++)
        #pragma unroll
        for (int i = 0; i < 4; i++) o[nt][i] = 0.f;
    float m0 = -1e30f, m1 = -1e30f, l0 = 0.f, l1 = 0.f;

    const uint32_t aQ = sb + (uint32_t)((wq + la.rA) * 72 + la.cA) * 2;

    for (int j = 0; j < SEQ / 128; j++) {
        const int b = j & 1;
        if (j + 1 < SEQ / 128) { stage_kv(b ^ 1, j + 1); CP_COMMIT(); CP_WAIT1(); }
        else                   { CP_WAIT0(); }
        __syncthreads();

        const uint32_t kbase = sb + (uint32_t)(KST_OFF + b * KSTAGE) * 2
                             + (uint32_t)(la.rB * 72 + la.cB) * 2;
        const uint32_t vbase = sb + (uint32_t)(VST_OFF + b * VSTAGE) * 2
                             + (uint32_t)(la.rB * 136 + la.cB) * 2;

        // ---- S = Q @ K^T (log2 domain) ----
        float s[16][4];
        #pragma unroll
        for (int nt = 0; nt < 16; nt++)
            #pragma unroll
            for (int i = 0; i < 4; i++) s[nt][i] = 0.f;

        #pragma unroll
        for (int ks = 0; ks < 4; ks++) {
            const uint32_t kk2 = (uint32_t)ks * 32;
            uint32_t ah[4], al[4];
            LDSM4(ah[0], ah[1], ah[2], ah[3], aQ + kk2);
            LDSM4(al[0], al[1], al[2], al[3], aQ + kk2 + QL_OFF * 2);
            #pragma unroll
            for (int ntp = 0; ntp < 8; ntp++) {
                uint32_t bb = kbase + (uint32_t)ntp * (16 * 72 * 2) + kk2;
                uint32_t h0a, h1a, h0b, h1b, l0a, l1a, l0b, l1b;
                LDSM4(h0a, h1a, h0b, h1b, bb);
                LDSM4(l0a, l1a, l0b, l1b, bb + 9216 * 2);
                MMA16816(s[2*ntp],   ah, h0a, h1a);
                MMA16816(s[2*ntp],   ah, l0a, l1a);
                MMA16816(s[2*ntp],   al, h0a, h1a);
                MMA16816(s[2*ntp+1], ah, h0b, h1b);
                MMA16816(s[2*ntp+1], ah, l0b, l1b);
                MMA16816(s[2*ntp+1], al, h0b, h1b);
            }
        }

        // ---- online softmax (rows g and g+8) ----
        float tm0 = -1e30f, tm1 = -1e30f;
        #pragma unroll
        for (int nt = 0; nt < 16; nt++) {
            tm0 = fmaxf(tm0, fmaxf(s[nt][0], s[nt][1]));
            tm1 = fmaxf(tm1, fmaxf(s[nt][2], s[nt][3]));
        }
        tm0 = fmaxf(tm0, __shfl_xor_sync(0xffffffffu, tm0, 1));
        tm0 = fmaxf(tm0, __shfl_xor_sync(0xffffffffu, tm0, 2));
        tm1 = fmaxf(tm1, __shfl_xor_sync(0xffffffffu, tm1, 1));
        tm1 = fmaxf(tm1, __shfl_xor_sync(0xffffffffu, tm1, 2));
        const float mn0 = fmaxf(m0, tm0), mn1 = fmaxf(m1, tm1);
        const float f0 = ex2f(m0 - mn0), f1 = ex2f(m1 - mn1);
        float sum0 = 0.f, sum1 = 0.f;
        #pragma unroll
        for (int nt = 0; nt < 16; nt++) {
            s[nt][0] = ex2f(s[nt][0] - mn0);
            s[nt][1] = ex2f(s[nt][1] - mn0);
            s[nt][2] = ex2f(s[nt][2] - mn1);
            s[nt][3] = ex2f(s[nt][3] - mn1);
            sum0 += s[nt][0] + s[nt][1];
            sum1 += s[nt][2] + s[nt][3];
        }
        sum0 += __shfl_xor_sync(0xffffffffu, sum0, 1);
        sum0 += __shfl_xor_sync(0xffffffffu, sum0, 2);
        sum1 += __shfl_xor_sync(0xffffffffu, sum1, 1);
        sum1 += __shfl_xor_sync(0xffffffffu, sum1, 2);
        l0 = l0 * f0 + sum0;  l1 = l1 * f1 + sum1;
        m0 = mn0;  m1 = mn1;
        #pragma unroll
        for (int nt = 0; nt < 8; nt++) {
            o[nt][0] *= f0; o[nt][1] *= f0;
            o[nt][2] *= f1; o[nt][3] *= f1;
        }

        // ---- O += P @ V (P split built from S fragments) ----
        #pragma unroll
        for (int kc = 0; kc < 8; kc++) {
            uint32_t ph[4], pl[4];
            split2(s[2*kc][0],   s[2*kc][1],   ph[0], pl[0]);
            split2(s[2*kc][2],   s[2*kc][3],   ph[1], pl[1]);
            split2(s[2*kc+1][0], s[2*kc+1][1], ph[2], pl[2]);
            split2(s[2*kc+1][2], s[2*kc+1][3], ph[3], pl[3]);
            const uint32_t kk2 = (uint32_t)kc * 32;
            #pragma unroll
            for (int ntp = 0; ntp < 4; ntp++) {
                uint32_t bb = vbase + (uint32_t)ntp * (16 * 136 * 2) + kk2;
                uint32_t h0a, h1a, h0b, h1b, l0a, l1a, l0b, l1b;
                LDSM4(h0a, h1a, h0b, h1b, bb);
                LDSM4(l0a, l1a, l0b, l1b, bb + 8704 * 2);
                MMA16816(o[2*ntp],   ph, h0a, h1a);
                MMA16816(o[2*ntp],   ph, l0a, l1a);
                MMA16816(o[2*ntp],   pl, h0a, h1a);
                MMA16816(o[2*ntp+1], ph, h0b, h1b);
                MMA16816(o[2*ntp+1], ph, l0b, l1b);
                MMA16816(o[2*ntp+1], pl, h0b, h1b);
            }
        }
        __syncthreads();
    }

    // ---- normalize + write bf16 hi/lo ----
    const float i0 = 1.f / l0, i1 = 1.f / l1;
    const int row = zb * SEQ + q0 + wq + g;
    #pragma unroll
    for (int nt = 0; nt < 8; nt++) {
        const int col = zh * 64 + nt * 8 + t * 2;
        uint32_t hp, lp;
        split2(o[nt][0] * i0, o[nt][1] * i0, hp, lp);
        *(uint32_t*)&outh[(size_t)row * EMBED + col] = hp;
        *(uint32_t*)&outl[(size_t)row * EMBED + col] = lp;
        split2(o[nt][2] * i1, o[nt][3] * i1, hp, lp);
        *(uint32_t*)&outh[(size_t)(row + 8) * EMBED + col] = hp;
        *(uint32_t*)&outl[(size_t)(row + 8) * EMBED + col] = lp;
    }
}

// ---------------- LayerNorm -> bf16 hi/lo ----------------
__global__ void ln_split(const float* __restrict__ x,
                         const float* __restrict__ gam,
                         const float* __restrict__ bet,
                         bf16* __restrict__ hi, bf16* __restrict__ lo) {
    int row = blockIdx.x;
    int t = threadIdx.x;
    const float4* xr = (const float4*)(x + (size_t)row * EMBED);
    float4 v = xr[t];
    float s  = v.x + v.y + v.z + v.w;
    float ss = v.x*v.x + v.y*v.y + v.z*v.z + v.w*v.w;
    #pragma unroll
    for (int o = 16; o; o >>= 1) {
        s  += __shfl_xor_sync(0xffffffffu, s,  o);
        ss += __shfl_xor_sync(0xffffffffu, ss, o);
    }
    __shared__ float shs[8], shs2[8];
    int w = t >> 5;
    if ((t & 31) == 0) { shs[w] = s; shs2[w] = ss; }
    __syncthreads();
    float tot = 0.f, tot2 = 0.f;
    #pragma unroll
    for (int i = 0; i < 8; i++) { tot += shs[i]; tot2 += shs2[i]; }
    float mu  = tot * (1.f / EMBED);
    float var = tot2 * (1.f / EMBED) - mu * mu;
    float rs  = rsqrtf(var + 1e-5f);
    float4 gv = ((const float4*)gam)[t];
    float4 bv = ((const float4*)bet)[t];
    float o0 = (v.x - mu) * rs * gv.x + bv.x;
    float o1 = (v.y - mu) * rs * gv.y + bv.y;
    float o2 = (v.z - mu) * rs * gv.z + bv.z;
    float o3 = (v.w - mu) * rs * gv.w + bv.w;
    uint32_t hp, lp;
    size_t base = (size_t)row * EMBED + t * 4;
    split2(o0, o1, hp, lp);
    *(uint32_t*)&hi[base] = hp;  *(uint32_t*)&lo[base] = lp;
    split2(o2, o3, hp, lp);
    *(uint32_t*)&hi[base + 2] = hp;  *(uint32_t*)&lo[base + 2] = lp;
}

// ---------------- conversions ----------------
// qkv [b,s,3072] -> q[z,s,d]*(0.125*log2e) and k[z,s,d]
__global__ void conv_qk(const float* __restrict__ qkv,
                        bf16* __restrict__ qh, bf16* __restrict__ ql,
                        bf16* __restrict__ kh, bf16* __restrict__ kl) {
    const float SCL = 0.125f * 1.4426950408889634f;
    size_t idx = (size_t)blockIdx.x * 256 + threadIdx.x;
    int d = idx & 63;
    int s = (idx >> 6) & 2047;
    int z = idx >> 17;
    int zb = z >> 4, zh = z & 15;
    size_t src = ((size_t)(zb * 2048 + s)) * QKVN + zh * 64 + d;
    bf16 h, l;
    split1(qkv[src] * SCL, h, l);   qh[idx] = h; ql[idx] = l;
    split1(qkv[src + 1024], h, l);  kh[idx] = h; kl[idx] = l;
}

// qkv V -> vT[z,d,s]
__global__ void conv_vT(const float* __restrict__ qkv,
                        bf16* __restrict__ vh, bf16* __restrict__ vl) {
    size_t idx = (size_t)blockIdx.x * 256 + threadIdx.x;
    int s = idx & 2047;
    int d = (idx >> 11) & 63;
    int z = idx >> 17;
    int zb = z >> 4, zh = z & 15;
    size_t src = ((size_t)(zb * 2048 + s)) * QKVN + 2048 + zh * 64 + d;
    bf16 h, l;
    split1(qkv[src], h, l);
    vh[idx] = h; vl[idx] = l;
}

// tiled transpose + split
__global__ void conv_T(const float* __restrict__ in,
                       bf16* __restrict__ hi, bf16* __restrict__ lo,
                       int K, int N, long inz, long outz) {
    __shared__ float t[32][33];
    in += (size_t)blockIdx.z * inz;
    hi += (size_t)blockIdx.z * outz;
    lo += (size_t)blockIdx.z * outz;
    int n0 = blockIdx.x * 32, k0 = blockIdx.y * 32;
    int tx = threadIdx.x, ty = threadIdx.y;    // (32, 8)
    #pragma unroll
    for (int j = 0; j < 32; j += 8)
        t[ty + j][tx] = in[(size_t)(k0 + ty + j) * N + n0 + tx];
    __syncthreads();
    #pragma unroll
    for (int j = 0; j < 32; j += 8) {
        float v = t[tx][ty + j];
        bf16 h, l; split1(v, h, l);
        size_t o = (size_t)(n0 + ty + j) * K + k0 + tx;
        hi[o] = h; lo[o] = l;
    }
}

// ---------------- launch ----------------
extern "C" void kernel_launch(void* const* d_in, const int* in_sizes, int n_in,
                              void* d_out, int out_size) {
    const float* x    = (const float*)d_in[0];
    const float* Wqkv = (const float*)d_in[1];
    const float* bqkv = (const float*)d_in[2];
    const float* Wo   = (const float*)d_in[3];
    const float* bo   = (const float*)d_in[4];
    const float* W1   = (const float*)d_in[5];
    const float* b1   = (const float*)d_in[6];
    const float* W2   = (const float*)d_in[7];
    const float* b2   = (const float*)d_in[8];
    const float* g1   = (const float*)d_in[9];
    const float* be1  = (const float*)d_in[10];
    const float* g2   = (const float*)d_in[11];
    const float* be2  = (const float*)d_in[12];
    float* out = (float*)d_out;

    float *qkv, *x2;
    cudaGetSymbolAddress((void**)&qkv, g_qkv);
    cudaGetSymbolAddress((void**)&x2,  g_x2);

    bf16 *nrm_h,*nrm_l,*wqkvT_h,*wqkvT_l,*q_h,*q_l,*k_h,*k_l,*vT_h,*vT_l;
    bf16 *attn_h,*attn_l,*woT_h,*woT_l,*n2_h,*n2_l;
    bf16 *w1T_h,*w1T_l,*ff1_h,*ff1_l,*w2T_h,*w2T_l;
    cudaGetSymbolAddress((void**)&nrm_h,   g_nrm_h);   cudaGetSymbolAddress((void**)&nrm_l,   g_nrm_l);
    cudaGetSymbolAddress((void**)&wqkvT_h, g_wqkvT_h); cudaGetSymbolAddress((void**)&wqkvT_l, g_wqkvT_l);
    cudaGetSymbolAddress((void**)&q_h,     g_q_h);     cudaGetSymbolAddress((void**)&q_l,     g_q_l);
    cudaGetSymbolAddress((void**)&k_h,     g_k_h);     cudaGetSymbolAddress((void**)&k_l,     g_k_l);
    cudaGetSymbolAddress((void**)&vT_h,    g_vT_h);    cudaGetSymbolAddress((void**)&vT_l,    g_vT_l);
    cudaGetSymbolAddress((void**)&attn_h,  g_attn_h);  cudaGetSymbolAddress((void**)&attn_l,  g_attn_l);
    cudaGetSymbolAddress((void**)&woT_h,   g_woT_h);   cudaGetSymbolAddress((void**)&woT_l,   g_woT_l);
    cudaGetSymbolAddress((void**)&n2_h,    g_n2_h);    cudaGetSymbolAddress((void**)&n2_l,    g_n2_l);
    cudaGetSymbolAddress((void**)&w1T_h,   g_w1T_h);   cudaGetSymbolAddress((void**)&w1T_l,   g_w1T_l);
    cudaGetSymbolAddress((void**)&ff1_h,   g_ff1_h);   cudaGetSymbolAddress((void**)&ff1_l,   g_ff1_l);
    cudaGetSymbolAddress((void**)&w2T_h,   g_w2T_h);   cudaGetSymbolAddress((void**)&w2T_l,   g_w2T_l);

    const int SMGEMM = 2 * (2*128 + 2*128) * 40 * 2;   // 81920 (2 CTAs/SM)
    const int SMFA   = (2*128*72 + 2*(2*128*72) + 2*(2*64*136)) * 2;  // 180224 (1 CTA/SM)
    cudaFuncSetAttribute(mma_gemm<true,false,false,false>, cudaFuncAttributeMaxDynamicSharedMemorySize, SMGEMM);
    cudaFuncSetAttribute(mma_gemm<true,true, false,false>, cudaFuncAttributeMaxDynamicSharedMemorySize, SMGEMM);
    cudaFuncSetAttribute(mma_gemm<true,false,true, true >, cudaFuncAttributeMaxDynamicSharedMemorySize, SMGEMM);
    cudaFuncSetAttribute(flash_attn, cudaFuncAttributeMaxDynamicSharedMemorySize, SMFA);

    dim3 tblk(32, 8);

    // launch order arranged so the ncu-captured slot (4th launch) is the QKV GEMM
    // 1) Wqkv transpose+split
    conv_T<<<dim3(2, 32, 48), tblk>>>(Wqkv, wqkvT_h, wqkvT_l, EMBED, HD, 65536, 65536);
    // 2) LN1 -> split
    ln_split<<<MTOK, 256>>>(x, g1, be1, nrm_h, nrm_l);
    // 3) Wo transpose+split
    conv_T<<<dim3(32, 32, 1), tblk>>>(Wo, woT_h, woT_l, EMBED, EMBED, 0, 0);
    // 4) QKV projection -> fp32 qkv (+bias)   <-- profiled slot
    mma_gemm<true,false,false,false><<<dim3(QKVN/128, MTOK/128), 256, SMGEMM>>>(
        nrm_h, nrm_l, wqkvT_h, wqkvT_l, bqkv, nullptr, qkv, nullptr, nullptr,
        EMBED, EMBED, EMBED, QKVN, 0);
    // 5-6) split Q (scaled), K, V^T
    conv_qk<<<(32*SEQ*HD)/256, 256>>>(qkv, q_h, q_l, k_h, k_l);
    conv_vT<<<(32*HD*SEQ)/256, 256>>>(qkv, vT_h, vT_l);
    // 7) fused attention -> attn hi/lo
    flash_attn<<<dim3(SEQ/128, 32), 256, SMFA>>>(
        q_h, q_l, k_h, k_l, vT_h, vT_l, attn_h, attn_l);
    // 8) O projection + bias + residual(x) -> x2
    mma_gemm<true,true,false,false><<<dim3(EMBED/128, MTOK/128), 256, SMGEMM>>>(
        attn_h, attn_l, woT_h, woT_l, bo, x, x2, nullptr, nullptr,
        EMBED, EMBED, EMBED, EMBED, EMBED);
    // 9) LN2 -> split
    ln_split<<<MTOK, 256>>>(x2, g2, be2, n2_h, n2_l);
    // 10) W1 transpose+split
    conv_T<<<dim3(128,32, 1), tblk>>>(W1, w1T_h, w1T_l, EMBED, FF, 0, 0);
    // 11) FF1 + bias + relu -> ff1 hi/lo
    mma_gemm<true,false,true,true><<<dim3(FF/128, MTOK/128), 256, SMGEMM>>>(
        n2_h, n2_l, w1T_h, w1T_l, b1, nullptr, nullptr, ff1_h, ff1_l,
        EMBED, EMBED, EMBED, FF, 0);
    // 12) W2 transpose+split
    conv_T<<<dim3(32,128, 1), tblk>>>(W2, w2T_h, w2T_l, FF, EMBED, 0, 0);
    // 13) FF2 + bias + residual(x2) -> out
    mma_gemm<true,true,false,false><<<dim3(EMBED/128, MTOK/128), 256, SMGEMM>>>(
        ff1_h, ff1_l, w2T_h, w2T_l, b2, x2, out, nullptr, nullptr,
        FF, FF, FF, EMBED, EMBED);
}